// round 12
// baseline (speedup 1.0000x reference)
#include <cuda_runtime.h>

#define B_   64
#define NI   2048
#define NO   32
#define DDO  16
#define DDI  16
#define OD   512
#define NBLK 148
#define THREADS 512

typedef unsigned long long ull;

// ---- shared memory (float offsets) ----
#define WT_PITCH 516
#define S_WT   0                         // W transposed [i][od], 16*516 = 8256
#define S_RAW  8256                      // raw W tile (natural), 8192 -> 16448
#define XD_PITCH_U 65                    // ull pitch
#define S_XD   16448                     // dup (x,x) ull [16][65] = 2080 -> 18528
#define S_XP   18528                     // natural x rows [64][20] = 1280 -> 19808
#define S_WS   19808                     // Wsum [16][33] = 528 -> 20336
#define S_CT   20336                     // c2 transposed [b][o] pitch 33 = 2112
#define SMEM_FLOATS 22448                // 89792 B

// dup-x column swizzle: b -> (b&3)*16 + (b>>2); for b = 4*bg+j this is 16*j + bg
#define XCOL(b) ((((b) & 3) << 4) | ((b) >> 2))

// partials: [seg][o][b][d] ; monotone grid-sync ticket
__device__ float    g_part[(size_t)NBLK * OD * B_];
__device__ unsigned g_cnt = 0;

__device__ __forceinline__ void fma2(ull& d, ull a, ull b) {
    asm("fma.rn.f32x2 %0, %1, %2, %0;" : "+l"(d) : "l"(a), "l"(b));
}
__device__ __forceinline__ ull mul2(ull a, ull b) {
    ull r; asm("mul.rn.f32x2 %0, %1, %2;" : "=l"(r) : "l"(a), "l"(b)); return r;
}
__device__ __forceinline__ ull pack_dup(float a) {
    ull r; asm("mov.b64 %0, {%1, %1};" : "=l"(r) : "f"(a)); return r;
}
__device__ __forceinline__ float2 unpk(ull a) {
    float2 r; asm("mov.b64 {%0, %1}, %2;" : "=f"(r.x), "=f"(r.y) : "l"(a)); return r;
}
__device__ __forceinline__ void cpa16(unsigned dst, const float* src) {
    asm volatile("cp.async.cg.shared.global [%0], [%1], 16;" :: "r"(dst), "l"(src));
}
__device__ __forceinline__ void cpa_commit() { asm volatile("cp.async.commit_group;"); }
__device__ __forceinline__ void cpa_wait0()  { asm volatile("cp.async.wait_group 0;"); }

extern "C" __global__ void __launch_bounds__(THREADS, 1)
capsule_main(const float* __restrict__ X, const float* __restrict__ W,
             float* __restrict__ out)
{
    extern __shared__ float sm[];
    float* sWs = sm + S_WS;
    float* sCT = sm + S_CT;

    const int tid  = threadIdx.x;
    const int lane = tid & 31;
    const int wid  = tid >> 5;
    const int o    = tid >> 4;               // contraction o (0..31), 2 per warp
    const int bg   = tid & 15;               // batches b = 4*bg + j, j<4
    const unsigned smem_u = (unsigned)__cvta_generic_to_shared(sm);

    // acc[p][j]: f32x2 over od = o*16 + 2p,2p+1 ; batch 4*bg + j   (64 regs)
    ull acc[8][4];
    #pragma unroll
    for (int p = 0; p < 8; p++)
        #pragma unroll
        for (int j = 0; j < 4; j++) acc[p][j] = 0ull;

    float4 xv;                               // x prefetch (tid<256): b=tid>>2, quad=tid&3

#define CPA_W(nn)                                                             \
    {                                                                         \
        const float* Wg = W + (size_t)(nn) * (OD * DDI);                      \
        unsigned base = smem_u + 4u * (unsigned)S_RAW;                        \
        _Pragma("unroll")                                                     \
        for (int k = 0; k < 4; k++) {                                         \
            int c = tid + k * THREADS;                                        \
            cpa16(base + 16u * (unsigned)c, Wg + 4 * c);                      \
        }                                                                     \
        cpa_commit();                                                         \
    }

#define LDX(nn)                                                               \
    if (tid < 256)                                                            \
        xv = *(const float4*)(X + ((size_t)(tid >> 2) * NI + (nn)) * DDI      \
                              + (tid & 3) * 4);

#define STAGE()                                                               \
    {                                                                         \
        const float4* rw = (const float4*)(sm + S_RAW);                       \
        _Pragma("unroll")                                                     \
        for (int k = 0; k < 4; k++) {                                         \
            int c = tid + k * THREADS;                                        \
            float4 v = rw[c];                                                 \
            int od = c >> 2, i0 = (c & 3) * 4;                                \
            float* w0 = sm + S_WT + od;                                       \
            w0[(i0 + 0) * WT_PITCH] = v.x;                                    \
            w0[(i0 + 1) * WT_PITCH] = v.y;                                    \
            w0[(i0 + 2) * WT_PITCH] = v.z;                                    \
            w0[(i0 + 3) * WT_PITCH] = v.w;                                    \
        }                                                                     \
        if (tid < 256) {                                                      \
            int b = tid >> 2, i0 = (tid & 3) * 4;                             \
            int xc = XCOL(b);                                                 \
            ull* xdu = (ull*)(sm + S_XD);                                     \
            xdu[(i0 + 0) * XD_PITCH_U + xc] = pack_dup(xv.x);                 \
            xdu[(i0 + 1) * XD_PITCH_U + xc] = pack_dup(xv.y);                 \
            xdu[(i0 + 2) * XD_PITCH_U + xc] = pack_dup(xv.z);                 \
            xdu[(i0 + 3) * XD_PITCH_U + xc] = pack_dup(xv.w);                 \
            *(float4*)(sm + S_XP + b * 20 + i0) = xv;                         \
        }                                                                     \
    }

#define WSUM()                                                                \
    {                                                                         \
        int oo = tid >> 4, ii = tid & 15;                                     \
        const float* r = sm + S_WT + ii * WT_PITCH + oo * 16;                 \
        float4 a = *(const float4*)(r);                                       \
        float4 b = *(const float4*)(r + 4);                                   \
        float4 c = *(const float4*)(r + 8);                                   \
        float4 d = *(const float4*)(r + 12);                                  \
        sWs[ii * 33 + oo] =                                                   \
            ((a.x + a.y) + (a.z + a.w)) + ((b.x + b.y) + (b.z + b.w)) +       \
            ((c.x + c.y) + (c.z + c.w)) + ((d.x + d.y) + (d.z + d.w));        \
    }

#define ROUTE()                                                               \
    {                                                                         \
        float ws[16];                                                         \
        _Pragma("unroll")                                                     \
        for (int i = 0; i < 16; i++) ws[i] = sWs[i * 33 + lane];              \
        _Pragma("unroll")                                                     \
        for (int bb = 0; bb < 4; bb++) {                                      \
            int b = wid * 4 + bb;                                             \
            const float* xp = sm + S_XP + b * 20;                             \
            float4 xa = *(const float4*)(xp);                                 \
            float4 xb = *(const float4*)(xp + 4);                             \
            float4 xc = *(const float4*)(xp + 8);                             \
            float4 xd = *(const float4*)(xp + 12);                            \
            float h = 0.f;                                                    \
            h = fmaf(ws[0], xa.x, h);  h = fmaf(ws[1], xa.y, h);              \
            h = fmaf(ws[2], xa.z, h);  h = fmaf(ws[3], xa.w, h);              \
            h = fmaf(ws[4], xb.x, h);  h = fmaf(ws[5], xb.y, h);              \
            h = fmaf(ws[6], xb.z, h);  h = fmaf(ws[7], xb.w, h);              \
            h = fmaf(ws[8], xc.x, h);  h = fmaf(ws[9], xc.y, h);              \
            h = fmaf(ws[10], xc.z, h); h = fmaf(ws[11], xc.w, h);             \
            h = fmaf(ws[12], xd.x, h); h = fmaf(ws[13], xd.y, h);             \
            h = fmaf(ws[14], xd.z, h); h = fmaf(ws[15], xd.w, h);             \
            float b1 = h * 0.03125f;                                          \
            float e1 = __expf(b1);                                            \
            float s1 = e1;                                                    \
            _Pragma("unroll")                                                 \
            for (int off = 16; off; off >>= 1)                                \
                s1 += __shfl_xor_sync(0xffffffffu, s1, off);                  \
            float b2 = fmaf(__fdividef(e1, s1), h, b1);                       \
            float e2 = __expf(b2);                                            \
            float s2 = e2;                                                    \
            _Pragma("unroll")                                                 \
            for (int off = 16; off; off >>= 1)                                \
                s2 += __shfl_xor_sync(0xffffffffu, s2, off);                  \
            sCT[b * 33 + lane] = __fdividef(e2, s2);   /* CT[b][o], 1-wf STS */\
        }                                                                     \
    }

    // ---------------- prologue ----------------
    int n = blockIdx.x;
    CPA_W(n);
    LDX(n);

    for (; n < NI; n += NBLK) {
        cpa_wait0();
        __syncthreads();                 // raw = W[n] ready; WT/XD/XP free

        STAGE();                         // raw -> WT, xv -> XD/XP
        {
            int n2 = n + NBLK;
            if (n2 < NI) LDX(n2);        // xv consumed by STAGE above
        }
        __syncthreads();                 // WT/XD/XP visible; raw fully read
        if (n + NBLK < NI) CPA_W(n + NBLK);   // refill raw; lands during route+contract

        WSUM();
        __syncthreads();                 // sWs visible
        ROUTE();
        __syncthreads();                 // sCT visible

        // ---- contraction: 16 od x 4 b per thread ----
        {
            ull c2d[4];
            #pragma unroll
            for (int j = 0; j < 4; j++)
                c2d[j] = pack_dup(sCT[(4 * bg + j) * 33 + o]);

            const ull*   xdu = (const ull*)(sm + S_XD);
            const float* wtb = sm + S_WT + o * 16;

            #pragma unroll
            for (int i = 0; i < DDI; i++) {
                const ull* xr = xdu + i * XD_PITCH_U + bg;  // cols 16j + bg
                ull xs0 = mul2(xr[0],  c2d[0]);
                ull xs1 = mul2(xr[16], c2d[1]);
                ull xs2 = mul2(xr[32], c2d[2]);
                ull xs3 = mul2(xr[48], c2d[3]);

                const float* wr = wtb + i * WT_PITCH;
                ulonglong2 wA = *(const ulonglong2*)(wr);
                ulonglong2 wB = *(const ulonglong2*)(wr + 4);
                ulonglong2 wC = *(const ulonglong2*)(wr + 8);
                ulonglong2 wD = *(const ulonglong2*)(wr + 12);

                fma2(acc[0][0], wA.x, xs0); fma2(acc[0][1], wA.x, xs1);
                fma2(acc[0][2], wA.x, xs2); fma2(acc[0][3], wA.x, xs3);
                fma2(acc[1][0], wA.y, xs0); fma2(acc[1][1], wA.y, xs1);
                fma2(acc[1][2], wA.y, xs2); fma2(acc[1][3], wA.y, xs3);
                fma2(acc[2][0], wB.x, xs0); fma2(acc[2][1], wB.x, xs1);
                fma2(acc[2][2], wB.x, xs2); fma2(acc[2][3], wB.x, xs3);
                fma2(acc[3][0], wB.y, xs0); fma2(acc[3][1], wB.y, xs1);
                fma2(acc[3][2], wB.y, xs2); fma2(acc[3][3], wB.y, xs3);
                fma2(acc[4][0], wC.x, xs0); fma2(acc[4][1], wC.x, xs1);
                fma2(acc[4][2], wC.x, xs2); fma2(acc[4][3], wC.x, xs3);
                fma2(acc[5][0], wC.y, xs0); fma2(acc[5][1], wC.y, xs1);
                fma2(acc[5][2], wC.y, xs2); fma2(acc[5][3], wC.y, xs3);
                fma2(acc[6][0], wD.x, xs0); fma2(acc[6][1], wD.x, xs1);
                fma2(acc[6][2], wD.x, xs2); fma2(acc[6][3], wD.x, xs3);
                fma2(acc[7][0], wD.y, xs0); fma2(acc[7][1], wD.y, xs1);
                fma2(acc[7][2], wD.y, xs2); fma2(acc[7][3], wD.y, xs3);
            }
        }
    }

    // ---- writeout partials: g_part[seg][o][b][d] ----
    {
        float* gp = g_part + (size_t)blockIdx.x * (OD * B_) + o * 1024;
        #pragma unroll
        for (int j = 0; j < 4; j++) {
            float* pj = gp + (4 * bg + j) * 16;
            float2 a0 = unpk(acc[0][j]); float2 a1 = unpk(acc[1][j]);
            float2 a2 = unpk(acc[2][j]); float2 a3 = unpk(acc[3][j]);
            float2 a4 = unpk(acc[4][j]); float2 a5 = unpk(acc[5][j]);
            float2 a6 = unpk(acc[6][j]); float2 a7 = unpk(acc[7][j]);
            *(float4*)(pj)      = make_float4(a0.x, a0.y, a1.x, a1.y);
            *(float4*)(pj + 4)  = make_float4(a2.x, a2.y, a3.x, a3.y);
            *(float4*)(pj + 8)  = make_float4(a4.x, a4.y, a5.x, a5.y);
            *(float4*)(pj + 12) = make_float4(a6.x, a6.y, a7.x, a7.y);
        }
    }

    // ---- software grid barrier (monotone ticket; graph-replay safe) ----
    __threadfence();
    __syncthreads();
    if (tid == 0) {
        unsigned t = atomicAdd(&g_cnt, 1u);
        unsigned target = (t / NBLK + 1u) * NBLK;
        while ((int)(*(volatile unsigned*)&g_cnt) - (int)target < 0) {}
        __threadfence();
    }
    __syncthreads();

    // ---- fused reduce + squash: 2 threads per float2-output, 74 segs each ----
    {
        const int g = blockIdx.x * THREADS + tid;
        if (g < 32768) {
            const int e    = g >> 1;               // float2 output 0..16383
            const int part = g & 1;

            const float2* p = ((const float2*)g_part) + (size_t)part * 16384 + e;
            float sx = 0.f, sy = 0.f;
            #pragma unroll
            for (int k = 0; k < 74; k++) {         // segs part, part+2, ...
                float2 v = __ldcg(p + (size_t)(2 * k) * 16384);
                sx += v.x; sy += v.y;
            }
            sx += __shfl_xor_sync(0xffffffffu, sx, 1);
            sy += __shfl_xor_sync(0xffffffffu, sy, 1);

            float qv = sx * sx + sy * sy;          // sum over 8 dp-groups
            qv += __shfl_xor_sync(0xffffffffu, qv, 2);
            qv += __shfl_xor_sync(0xffffffffu, qv, 4);
            qv += __shfl_xor_sync(0xffffffffu, qv, 8);
            float s2 = qv;

            if (part == 0) {
                float scale = s2 / ((1.f + s2) * sqrtf(s2 + 1e-7f));
                int oo = e >> 9, bb = (e >> 3) & 63, dp = e & 7;
                *(float2*)(out + (size_t)bb * (NO * DDO) + oo * 16 + 2 * dp) =
                    make_float2(scale * sx, scale * sy);
            }
        }
    }
}

extern "C" void kernel_launch(void* const* d_in, const int* in_sizes, int n_in,
                              void* d_out, int out_size)
{
    const float* a = (const float*)d_in[0];
    const float* c = (const float*)d_in[1];
    const float *X, *W;
    if (in_sizes[0] == B_ * NI * DDI) { X = a; W = c; }
    else                              { X = c; W = a; }

    size_t smem = (size_t)SMEM_FLOATS * sizeof(float);
    cudaFuncSetAttribute(capsule_main,
                         cudaFuncAttributeMaxDynamicSharedMemorySize, (int)smem);
    capsule_main<<<NBLK, THREADS, smem>>>(X, W, (float*)d_out);
}

// round 14
// speedup vs baseline: 1.6795x; 1.6795x over previous
#include <cuda_runtime.h>
#include <cstdint>

#define B_   64
#define NI   2048
#define NO   32
#define DDO  16
#define DDI  16
#define OD   512
#define NBLK 148
#define THREADS 512

typedef unsigned long long ull;

// ---- shared memory (float offsets) ----
#define S_W0   0        // W buf0: [512 od][20] = 10240
#define S_W1   10240    // W buf1
#define S_XT   20480    // x transposed [16 i][72] = 1152
#define S_XP   21632    // natural x rows [64 b][20] = 1280
#define S_WS   22912    // Wsum [16][33] = 528
#define S_CT   23440    // c2 transposed [64 b][33] = 2112
#define SMEM_FLOATS 25552   // 102208 B

#define WBUF(b) ((b) ? S_W1 : S_W0)

// partials: [seg][o][b][d] ; monotone grid-sync ticket
__device__ float    g_part[(size_t)NBLK * OD * B_];
__device__ unsigned g_cnt = 0;

__device__ __forceinline__ void fma2(ull& d, ull a, ull b) {
    asm("fma.rn.f32x2 %0, %1, %2, %0;" : "+l"(d) : "l"(a), "l"(b));
}
__device__ __forceinline__ ull pk2f(float a, float b) {
    ull r; asm("mov.b64 %0, {%1, %2};" : "=l"(r) : "f"(a), "f"(b)); return r;
}
__device__ __forceinline__ float2 unpk(ull a) {
    float2 r; asm("mov.b64 {%0, %1}, %2;" : "=f"(r.x), "=f"(r.y) : "l"(a)); return r;
}
__device__ __forceinline__ uint32_t f2tf(float a) {
    uint32_t r; asm("cvt.rn.tf32.f32 %0, %1;" : "=r"(r) : "f"(a)); return r;
}
__device__ __forceinline__ void cpa16(unsigned dst, const float* src) {
    asm volatile("cp.async.cg.shared.global [%0], [%1], 16;" :: "r"(dst), "l"(src));
}
__device__ __forceinline__ void cpa_commit() { asm volatile("cp.async.commit_group;"); }
__device__ __forceinline__ void cpa_wait0()  { asm volatile("cp.async.wait_group 0;"); }

#define MMA_TF32(d0, d1, d2, d3, a, b0, b1)                                   \
    asm volatile(                                                             \
        "mma.sync.aligned.m16n8k8.row.col.f32.tf32.tf32.f32 "                 \
        "{%0,%1,%2,%3}, {%4,%5,%6,%7}, {%8,%9}, {%0,%1,%2,%3};"               \
        : "+f"(d0), "+f"(d1), "+f"(d2), "+f"(d3)                              \
        : "r"((a)[0]), "r"((a)[1]), "r"((a)[2]), "r"((a)[3]),                 \
          "r"(b0), "r"(b1))

extern "C" __global__ void __launch_bounds__(THREADS, 1)
capsule_main(const float* __restrict__ X, const float* __restrict__ W,
             float* __restrict__ out)
{
    extern __shared__ float sm[];
    float* sWs = sm + S_WS;
    float* sCT = sm + S_CT;

    const int tid  = threadIdx.x;
    const int lane = tid & 31;
    const int wid  = tid >> 5;
    const int g    = lane >> 2;              // mma groupID
    const int t    = lane & 3;               // mma threadID-in-group
    const unsigned smem_u = (unsigned)__cvta_generic_to_shared(sm);

    // acc[mi][n][rh]: f32x2 over (b = n*8+2t, b+1); od = wid*32+mi*16+g+8*rh
    ull acc[2][8][2];
    #pragma unroll
    for (int mi = 0; mi < 2; mi++)
        #pragma unroll
        for (int j = 0; j < 8; j++) { acc[mi][j][0] = 0ull; acc[mi][j][1] = 0ull; }

    float4 xv;                               // x prefetch (tid<256)

#define CPA_W(nn, bf)                                                         \
    {                                                                         \
        const float* Wg = W + (size_t)(nn) * (OD * DDI);                      \
        unsigned wb = smem_u + 4u * (unsigned)WBUF(bf);                       \
        _Pragma("unroll")                                                     \
        for (int k = 0; k < 4; k++) {                                         \
            int c = tid + k * THREADS;       /* c = od*4 + q */               \
            unsigned od = (unsigned)(c >> 2), q = (unsigned)(c & 3);          \
            cpa16(wb + od * 80u + q * 16u, Wg + 4 * c);                       \
        }                                                                     \
        cpa_commit();                                                         \
    }

#define LDX(nn)                                                               \
    if (tid < 256)                                                            \
        xv = *(const float4*)(X + ((size_t)(tid >> 2) * NI + (nn)) * DDI      \
                              + (tid & 3) * 4);

#define STAGE_X()                                                             \
    if (tid < 256) {                                                          \
        int b = tid >> 2, q = tid & 3;                                        \
        float* xtp = sm + S_XT + b;                                           \
        xtp[(q * 4 + 0) * 72] = xv.x;                                         \
        xtp[(q * 4 + 1) * 72] = xv.y;                                         \
        xtp[(q * 4 + 2) * 72] = xv.z;                                         \
        xtp[(q * 4 + 3) * 72] = xv.w;                                         \
        *(float4*)(sm + S_XP + b * 20 + q * 4) = xv;                          \
    }

#define WSUM(bf)                                                              \
    {                                                                         \
        int oo = tid >> 4, ii = tid & 15;                                     \
        const float* wb = sm + WBUF(bf) + oo * 320 + ii;                      \
        float s = 0.f;                                                        \
        _Pragma("unroll")                                                     \
        for (int d2 = 0; d2 < 16; d2++) s += wb[d2 * 20];                     \
        sWs[ii * 33 + oo] = s;                                                \
    }

#define ROUTE()                                                               \
    {                                                                         \
        float ws[16];                                                         \
        _Pragma("unroll")                                                     \
        for (int i = 0; i < 16; i++) ws[i] = sWs[i * 33 + lane];              \
        _Pragma("unroll")                                                     \
        for (int bb = 0; bb < 4; bb++) {                                      \
            int b = wid * 4 + bb;                                             \
            const float* xp = sm + S_XP + b * 20;                             \
            float4 xa = *(const float4*)(xp);                                 \
            float4 xb = *(const float4*)(xp + 4);                             \
            float4 xc = *(const float4*)(xp + 8);                             \
            float4 xd = *(const float4*)(xp + 12);                            \
            float h = 0.f;                                                    \
            h = fmaf(ws[0], xa.x, h);   h = fmaf(ws[1], xa.y, h);             \
            h = fmaf(ws[2], xa.z, h);   h = fmaf(ws[3], xa.w, h);             \
            h = fmaf(ws[4], xb.x, h);   h = fmaf(ws[5], xb.y, h);             \
            h = fmaf(ws[6], xb.z, h);   h = fmaf(ws[7], xb.w, h);             \
            h = fmaf(ws[8], xc.x, h);   h = fmaf(ws[9], xc.y, h);             \
            h = fmaf(ws[10], xc.z, h);  h = fmaf(ws[11], xc.w, h);            \
            h = fmaf(ws[12], xd.x, h);  h = fmaf(ws[13], xd.y, h);            \
            h = fmaf(ws[14], xd.z, h);  h = fmaf(ws[15], xd.w, h);            \
            float b1 = h * 0.03125f;                                          \
            float e1 = __expf(b1);                                            \
            float s1 = e1;                                                    \
            _Pragma("unroll")                                                 \
            for (int off = 16; off; off >>= 1)                                \
                s1 += __shfl_xor_sync(0xffffffffu, s1, off);                  \
            float b2 = fmaf(__fdividef(e1, s1), h, b1);                       \
            float e2 = __expf(b2);                                            \
            float s2 = e2;                                                    \
            _Pragma("unroll")                                                 \
            for (int off = 16; off; off >>= 1)                                \
                s2 += __shfl_xor_sync(0xffffffffu, s2, off);                  \
            sCT[b * 33 + lane] = __fdividef(e2, s2);  /* CT[b][o], bank-clean */ \
        }                                                                     \
    }

    // ---------------- prologue ----------------
    int n = blockIdx.x;
    CPA_W(n, 0);
    LDX(n);

    for (int it = 0; n < NI; it++, n += NBLK) {
        const int buf = it & 1;
        cpa_wait0();
        __syncthreads();                 // W[buf] arrived; prev readers of XT/XP/sCT done

        STAGE_X();                       // xv -> XT (i-major) + XP (b-major)
        WSUM(buf);                       // W[buf] natural rows -> sWs
        if (n + NBLK < NI) LDX(n + NBLK);
        __syncthreads();                 // XT/XP/sWs visible
        if (n + NBLK < NI) CPA_W(n + NBLK, buf ^ 1);

        ROUTE();                         // sWs + XP -> sCT
        __syncthreads();                 // sCT visible

        // ---- tensor contraction: G = W·xᵀ via mma.sync, then c2-scale ----
        {
            const float* wb = sm + WBUF(buf);
            const float* xt = sm + S_XT;

            uint32_t A[2][2][4];         // [mi][k][frag]
            #pragma unroll
            for (int mi = 0; mi < 2; mi++) {
                const float* wr = wb + (wid * 32 + mi * 16 + g) * 20;
                #pragma unroll
                for (int k = 0; k < 2; k++) {
                    int c0 = k * 8 + t;
                    A[mi][k][0] = f2tf(wr[c0]);
                    A[mi][k][1] = f2tf(wr[160 + c0]);       // row +8 -> +8*20
                    A[mi][k][2] = f2tf(wr[c0 + 4]);
                    A[mi][k][3] = f2tf(wr[160 + c0 + 4]);
                }
            }
            #pragma unroll
            for (int nn2 = 0; nn2 < 8; nn2++) {
                int bcol = nn2 * 8 + g;
                uint32_t B00 = f2tf(xt[t * 72 + bcol]);           // k0: rows t, t+4
                uint32_t B01 = f2tf(xt[(t + 4) * 72 + bcol]);
                uint32_t B10 = f2tf(xt[(t + 8) * 72 + bcol]);     // k1: rows 8+t, 12+t
                uint32_t B11 = f2tf(xt[(t + 12) * 72 + bcol]);
                #pragma unroll
                for (int mi = 0; mi < 2; mi++) {
                    float d0 = 0.f, d1 = 0.f, d2 = 0.f, d3 = 0.f;
                    MMA_TF32(d0, d1, d2, d3, A[mi][0], B00, B01);
                    MMA_TF32(d0, d1, d2, d3, A[mi][1], B10, B11);
                    int o2 = wid * 2 + mi;
                    int b0 = nn2 * 8 + 2 * t;
                    float cx = sCT[b0 * 33 + o2];
                    float cy = sCT[(b0 + 1) * 33 + o2];
                    ull c2p = pk2f(cx, cy);
                    fma2(acc[mi][nn2][0], c2p, pk2f(d0, d1));   // row g
                    fma2(acc[mi][nn2][1], c2p, pk2f(d2, d3));   // row g+8
                }
            }
        }
    }

    // ---- writeout partials: g_part[seg][o][b][d] ----
    {
        float* gp = g_part + (size_t)blockIdx.x * (OD * B_) + (wid * 2) * 1024;
        #pragma unroll
        for (int mi = 0; mi < 2; mi++)
            #pragma unroll
            for (int nn2 = 0; nn2 < 8; nn2++) {
                float2 lo = unpk(acc[mi][nn2][0]);   // (b0, g), (b0+1, g)
                float2 hi = unpk(acc[mi][nn2][1]);   // (b0, g+8), (b0+1, g+8)
                float* p = gp + mi * 1024 + (nn2 * 8 + 2 * t) * 16;
                p[g]          = lo.x;
                p[g + 8]      = hi.x;
                p[16 + g]     = lo.y;
                p[16 + g + 8] = hi.y;
            }
    }

    // ---- software grid barrier (monotone ticket; graph-replay safe) ----
    __threadfence();
    __syncthreads();
    if (tid == 0) {
        unsigned tk = atomicAdd(&g_cnt, 1u);
        unsigned target = (tk / NBLK + 1u) * NBLK;
        while ((int)(*(volatile unsigned*)&g_cnt) - (int)target < 0) {}
        __threadfence();
    }
    __syncthreads();

    // ---- fused reduce + squash: 2 threads per float2-output, 74 segs each ----
    {
        const int gg = blockIdx.x * THREADS + tid;
        if (gg < 32768) {
            const int e    = gg >> 1;
            const int part = gg & 1;

            const float2* p = ((const float2*)g_part) + (size_t)part * 16384 + e;
            float sx = 0.f, sy = 0.f;
            #pragma unroll
            for (int k = 0; k < 74; k++) {
                float2 v = __ldcg(p + (size_t)(2 * k) * 16384);
                sx += v.x; sy += v.y;
            }
            sx += __shfl_xor_sync(0xffffffffu, sx, 1);
            sy += __shfl_xor_sync(0xffffffffu, sy, 1);

            float qv = sx * sx + sy * sy;
            qv += __shfl_xor_sync(0xffffffffu, qv, 2);
            qv += __shfl_xor_sync(0xffffffffu, qv, 4);
            qv += __shfl_xor_sync(0xffffffffu, qv, 8);
            float s2 = qv;

            if (part == 0) {
                float scale = s2 / ((1.f + s2) * sqrtf(s2 + 1e-7f));
                int o2 = e >> 9, bb = (e >> 3) & 63, dp = e & 7;
                *(float2*)(out + (size_t)bb * (NO * DDO) + o2 * 16 + 2 * dp) =
                    make_float2(scale * sx, scale * sy);
            }
        }
    }
}

extern "C" void kernel_launch(void* const* d_in, const int* in_sizes, int n_in,
                              void* d_out, int out_size)
{
    const float* a = (const float*)d_in[0];
    const float* c = (const float*)d_in[1];
    const float *X, *W;
    if (in_sizes[0] == B_ * NI * DDI) { X = a; W = c; }
    else                              { X = c; W = a; }

    size_t smem = (size_t)SMEM_FLOATS * sizeof(float);
    cudaFuncSetAttribute(capsule_main,
                         cudaFuncAttributeMaxDynamicSharedMemorySize, (int)smem);
    capsule_main<<<NBLK, THREADS, smem>>>(X, W, (float*)d_out);
}

// round 16
// speedup vs baseline: 1.8152x; 1.0808x over previous
#include <cuda_runtime.h>
#include <cstdint>

#define B_   64
#define NI   2048
#define NO   32
#define DDO  16
#define DDI  16
#define OD   512
#define NBLK 148
#define THREADS 512

typedef unsigned long long ull;

// ---- shared memory (float offsets) ----
#define S_W0   0        // W buf0: [512 od][20] = 10240
#define S_W1   10240    // W buf1
#define S_XF   20480    // packed tf32 B-frags: [64 bcol][48 words] = 3072
#define S_XP   23552    // natural x rows [64 b][20] = 1280
#define S_WS   24832    // Wsum [16][33] = 528
#define S_CT   25360    // c2 [o][b] pitch 68 = 2176
#define SMEM_FLOATS 27536   // 110144 B

#define WBUF(b) ((b) ? S_W1 : S_W0)

// partials: [seg][o][b][d] ; monotone grid-sync ticket
__device__ float    g_part[(size_t)NBLK * OD * B_];
__device__ unsigned g_cnt = 0;

__device__ __forceinline__ void fma2(ull& d, ull a, ull b) {
    asm("fma.rn.f32x2 %0, %1, %2, %0;" : "+l"(d) : "l"(a), "l"(b));
}
__device__ __forceinline__ ull pk2f(float a, float b) {
    ull r; asm("mov.b64 %0, {%1, %2};" : "=l"(r) : "f"(a), "f"(b)); return r;
}
__device__ __forceinline__ float2 unpk(ull a) {
    float2 r; asm("mov.b64 {%0, %1}, %2;" : "=f"(r.x), "=f"(r.y) : "l"(a)); return r;
}
__device__ __forceinline__ uint32_t f2tf(float a) {
    uint32_t r; asm("cvt.rn.tf32.f32 %0, %1;" : "=r"(r) : "f"(a)); return r;
}
__device__ __forceinline__ void cpa16(unsigned dst, const float* src) {
    asm volatile("cp.async.cg.shared.global [%0], [%1], 16;" :: "r"(dst), "l"(src));
}
__device__ __forceinline__ void cpa_commit() { asm volatile("cp.async.commit_group;"); }
__device__ __forceinline__ void cpa_wait0()  { asm volatile("cp.async.wait_group 0;"); }

#define MMA_TF32(d0, d1, d2, d3, a, b0, b1)                                   \
    asm volatile(                                                             \
        "mma.sync.aligned.m16n8k8.row.col.f32.tf32.tf32.f32 "                 \
        "{%0,%1,%2,%3}, {%4,%5,%6,%7}, {%8,%9}, {%0,%1,%2,%3};"               \
        : "+f"(d0), "+f"(d1), "+f"(d2), "+f"(d3)                              \
        : "r"((a)[0]), "r"((a)[1]), "r"((a)[2]), "r"((a)[3]),                 \
          "r"(b0), "r"(b1))

extern "C" __global__ void __launch_bounds__(THREADS, 1)
capsule_main(const float* __restrict__ X, const float* __restrict__ W,
             float* __restrict__ out)
{
    extern __shared__ float sm[];
    float* sWs = sm + S_WS;
    float* sCT = sm + S_CT;

    const int tid  = threadIdx.x;
    const int lane = tid & 31;
    const int wid  = tid >> 5;
    const int g    = lane >> 2;              // mma groupID
    const int t    = lane & 3;               // mma threadID-in-group
    const unsigned smem_u = (unsigned)__cvta_generic_to_shared(sm);

    // acc[mi][n][rh]: f32x2 over (b = n*8+2t, b+1); od = wid*32+mi*16+g+8*rh
    ull acc[2][8][2];
    #pragma unroll
    for (int mi = 0; mi < 2; mi++)
        #pragma unroll
        for (int j = 0; j < 8; j++) { acc[mi][j][0] = 0ull; acc[mi][j][1] = 0ull; }

    float4 xv;                               // x prefetch (tid<256)

#define CPA_W(nn, bf)                                                         \
    {                                                                         \
        const float* Wg = W + (size_t)(nn) * (OD * DDI);                      \
        unsigned wb = smem_u + 4u * (unsigned)WBUF(bf);                       \
        _Pragma("unroll")                                                     \
        for (int k = 0; k < 4; k++) {                                         \
            int c = tid + k * THREADS;       /* c = od*4 + q */               \
            unsigned od = (unsigned)(c >> 2), q = (unsigned)(c & 3);          \
            cpa16(wb + od * 80u + q * 16u, Wg + 4 * c);                       \
        }                                                                     \
        cpa_commit();                                                         \
    }

#define LDX(nn)                                                               \
    if (tid < 256)                                                            \
        xv = *(const float4*)(X + ((size_t)(tid >> 2) * NI + (nn)) * DDI      \
                              + (tid & 3) * 4);

// pack tf32 B-fragments: xf[b][slot ((r+b)&3)][word q] = tf32(x[b][4q+r])
#define STAGE_X()                                                             \
    if (tid < 256) {                                                          \
        int b = tid >> 2, q = tid & 3;                                        \
        uint32_t* xf = (uint32_t*)(sm + S_XF) + b * 48 + q;                   \
        xf[(((0 + b) & 3) << 2)] = f2tf(xv.x);                                \
        xf[(((1 + b) & 3) << 2)] = f2tf(xv.y);                                \
        xf[(((2 + b) & 3) << 2)] = f2tf(xv.z);                                \
        xf[(((3 + b) & 3) << 2)] = f2tf(xv.w);                                \
        *(float4*)(sm + S_XP + b * 20 + q * 4) = xv;                          \
    }

#define WSUM(bf)                                                              \
    {                                                                         \
        int oo = tid >> 4, ii = tid & 15;                                     \
        const float* wb = sm + WBUF(bf) + oo * 320 + ii;                      \
        float s = 0.f;                                                        \
        _Pragma("unroll")                                                     \
        for (int d2 = 0; d2 < 16; d2++) s += wb[d2 * 20];                     \
        sWs[ii * 33 + oo] = s;                                                \
    }

#define ROUTE()                                                               \
    {                                                                         \
        float ws[16];                                                         \
        _Pragma("unroll")                                                     \
        for (int i = 0; i < 16; i++) ws[i] = sWs[i * 33 + lane];              \
        _Pragma("unroll")                                                     \
        for (int bb = 0; bb < 4; bb++) {                                      \
            int b = wid * 4 + bb;                                             \
            const float* xp = sm + S_XP + b * 20;                             \
            float4 xa = *(const float4*)(xp);                                 \
            float4 xb = *(const float4*)(xp + 4);                             \
            float4 xc = *(const float4*)(xp + 8);                             \
            float4 xd = *(const float4*)(xp + 12);                            \
            float h = 0.f;                                                    \
            h = fmaf(ws[0], xa.x, h);   h = fmaf(ws[1], xa.y, h);             \
            h = fmaf(ws[2], xa.z, h);   h = fmaf(ws[3], xa.w, h);             \
            h = fmaf(ws[4], xb.x, h);   h = fmaf(ws[5], xb.y, h);             \
            h = fmaf(ws[6], xb.z, h);   h = fmaf(ws[7], xb.w, h);             \
            h = fmaf(ws[8], xc.x, h);   h = fmaf(ws[9], xc.y, h);             \
            h = fmaf(ws[10], xc.z, h);  h = fmaf(ws[11], xc.w, h);            \
            h = fmaf(ws[12], xd.x, h);  h = fmaf(ws[13], xd.y, h);            \
            h = fmaf(ws[14], xd.z, h);  h = fmaf(ws[15], xd.w, h);            \
            float b1 = h * 0.03125f;                                          \
            float e1 = __expf(b1);                                            \
            float s1 = e1;                                                    \
            _Pragma("unroll")                                                 \
            for (int off = 16; off; off >>= 1)                                \
                s1 += __shfl_xor_sync(0xffffffffu, s1, off);                  \
            float b2 = fmaf(__fdividef(e1, s1), h, b1);                       \
            float e2 = __expf(b2);                                            \
            float s2 = e2;                                                    \
            _Pragma("unroll")                                                 \
            for (int off = 16; off; off >>= 1)                                \
                s2 += __shfl_xor_sync(0xffffffffu, s2, off);                  \
            sCT[lane * 68 + b] = __fdividef(e2, s2);   /* [o][b] */           \
        }                                                                     \
    }

    // ---------------- prologue ----------------
    int n = blockIdx.x;
    CPA_W(n, 0);
    LDX(n);

    for (int it = 0; n < NI; it++, n += NBLK) {
        const int buf = it & 1;
        cpa_wait0();
        __syncthreads();                 // W[buf] arrived; prev readers of XF/XP/sCT done

        STAGE_X();                       // xv -> XF (tf32 frags) + XP (b-major)
        WSUM(buf);                       // W[buf] natural rows -> sWs
        if (n + NBLK < NI) LDX(n + NBLK);
        __syncthreads();                 // XF/XP/sWs visible
        if (n + NBLK < NI) CPA_W(n + NBLK, buf ^ 1);

        ROUTE();                         // sWs + XP -> sCT
        __syncthreads();                 // sCT visible

        // ---- tensor contraction: G = W·xᵀ via mma.sync, then c2-scale ----
        {
            const float* wb = sm + WBUF(buf);
            const uint4* xf = (const uint4*)(sm + S_XF);

            uint32_t A[2][2][4];         // [mi][k][frag]
            #pragma unroll
            for (int mi = 0; mi < 2; mi++) {
                const float* wr = wb + (wid * 32 + mi * 16 + g) * 20;
                #pragma unroll
                for (int k = 0; k < 2; k++) {
                    int c0 = k * 8 + t;
                    A[mi][k][0] = f2tf(wr[c0]);
                    A[mi][k][1] = f2tf(wr[160 + c0]);       // row +8
                    A[mi][k][2] = f2tf(wr[c0 + 4]);
                    A[mi][k][3] = f2tf(wr[160 + c0 + 4]);
                }
            }
            #pragma unroll
            for (int nn2 = 0; nn2 < 8; nn2++) {
                int bcol = nn2 * 8 + g;
                uint4 B4 = xf[bcol * 12 + ((t + bcol) & 3)];
                // B4 = rows {t, t+4, t+8, t+12} of column bcol (tf32)
                #pragma unroll
                for (int mi = 0; mi < 2; mi++) {
                    float d0 = 0.f, d1 = 0.f, d2 = 0.f, d3 = 0.f;
                    MMA_TF32(d0, d1, d2, d3, A[mi][0], B4.x, B4.y);
                    MMA_TF32(d0, d1, d2, d3, A[mi][1], B4.z, B4.w);
                    int o2 = wid * 2 + mi;
                    int b0 = nn2 * 8 + 2 * t;
                    ull c2p = *(const ull*)(sCT + o2 * 68 + b0);   // (cx, cy)
                    fma2(acc[mi][nn2][0], c2p, pk2f(d0, d1));   // row g
                    fma2(acc[mi][nn2][1], c2p, pk2f(d2, d3));   // row g+8
                }
            }
        }
    }

    // ---- writeout partials: g_part[seg][o][b][d] ----
    {
        float* gp = g_part + (size_t)blockIdx.x * (OD * B_) + (wid * 2) * 1024;
        #pragma unroll
        for (int mi = 0; mi < 2; mi++)
            #pragma unroll
            for (int nn2 = 0; nn2 < 8; nn2++) {
                float2 lo = unpk(acc[mi][nn2][0]);   // (b0, g), (b0+1, g)
                float2 hi = unpk(acc[mi][nn2][1]);   // (b0, g+8), (b0+1, g+8)
                float* p = gp + mi * 1024 + (nn2 * 8 + 2 * t) * 16;
                p[g]          = lo.x;
                p[g + 8]      = hi.x;
                p[16 + g]     = lo.y;
                p[16 + g + 8] = hi.y;
            }
    }

    // ---- software grid barrier (monotone ticket; graph-replay safe) ----
    __threadfence();
    __syncthreads();
    if (tid == 0) {
        unsigned tk = atomicAdd(&g_cnt, 1u);
        unsigned target = (tk / NBLK + 1u) * NBLK;
        while ((int)(*(volatile unsigned*)&g_cnt) - (int)target < 0) {}
        __threadfence();
    }
    __syncthreads();

    // ---- fused reduce + squash: 2 threads per float2-output, 74 segs each ----
    {
        const int gg = blockIdx.x * THREADS + tid;
        if (gg < 32768) {
            const int e    = gg >> 1;
            const int part = gg & 1;

            const float2* p = ((const float2*)g_part) + (size_t)part * 16384 + e;
            float sx = 0.f, sy = 0.f;
            #pragma unroll
            for (int k = 0; k < 74; k++) {
                float2 v = __ldcg(p + (size_t)(2 * k) * 16384);
                sx += v.x; sy += v.y;
            }
            sx += __shfl_xor_sync(0xffffffffu, sx, 1);
            sy += __shfl_xor_sync(0xffffffffu, sy, 1);

            float qv = sx * sx + sy * sy;
            qv += __shfl_xor_sync(0xffffffffu, qv, 2);
            qv += __shfl_xor_sync(0xffffffffu, qv, 4);
            qv += __shfl_xor_sync(0xffffffffu, qv, 8);
            float s2 = qv;

            if (part == 0) {
                float scale = s2 / ((1.f + s2) * sqrtf(s2 + 1e-7f));
                int o2 = e >> 9, bb = (e >> 3) & 63, dp = e & 7;
                *(float2*)(out + (size_t)bb * (NO * DDO) + o2 * 16 + 2 * dp) =
                    make_float2(scale * sx, scale * sy);
            }
        }
    }
}

extern "C" void kernel_launch(void* const* d_in, const int* in_sizes, int n_in,
                              void* d_out, int out_size)
{
    const float* a = (const float*)d_in[0];
    const float* c = (const float*)d_in[1];
    const float *X, *W;
    if (in_sizes[0] == B_ * NI * DDI) { X = a; W = c; }
    else                              { X = c; W = a; }

    size_t smem = (size_t)SMEM_FLOATS * sizeof(float);
    cudaFuncSetAttribute(capsule_main,
                         cudaFuncAttributeMaxDynamicSharedMemorySize, (int)smem);
    capsule_main<<<NBLK, THREADS, smem>>>(X, W, (float*)d_out);
}